// round 9
// baseline (speedup 1.0000x reference)
#include <cuda_runtime.h>
#include <cuda_bf16.h>
#include <math.h>

// ---------------- problem constants ----------------
#define NN      20000
#define EP      120000
#define EN      600000
#define ET      720000
#define E2      240000
#define LN_EPS  1e-5f

// ---------------- scratch ----------------
__device__ float  g_M1[NN * 256];   // x@W1
__device__ float  g_H1[NN * 256];   // relu(LN(gather+b1))
__device__ float  g_M2[NN * 128];   // h1@[Wmu|Wlv]
__device__ float  g_Z [NN * 64];    // latent
__device__ float  g_M3[NN * 64];    // decoder gemm scratch
__device__ float  g_HD1[NN * 64];   // decoder hidden 1 (post act)
__device__ float  g_HF [NN * 64];   // decoder hidden 2 fp32
__device__ __nv_bfloat16 g_Hbf[NN * 64];
__device__ __nv_bfloat16 g_Pbf[NN * 128];
// CSR
__device__ int    g_edeg[NN], g_ddeg[NN];
__device__ int    g_eoff[NN + 1], g_doff[NN + 1];
__device__ int    g_ecur[NN], g_dcur[NN];
__device__ int    g_esrc[E2], g_dsrc[EP];
__device__ float  g_dis[NN];
__device__ double g_acc[2];

// ---------------- helpers ----------------
__device__ __forceinline__ float logsig(float x) {
    return fminf(x, 0.0f) - log1pf(expf(-fabsf(x)));
}
__device__ __forceinline__ unsigned f2tf32(float x) {
    unsigned r;
    asm("cvt.rna.tf32.f32 %0, %1;" : "=r"(r) : "f"(x));
    return r;
}
__device__ __forceinline__ void mma_tf32(float& d0, float& d1, float& d2, float& d3,
                                         unsigned a0, unsigned a1, unsigned a2, unsigned a3,
                                         unsigned b0, unsigned b1) {
    asm volatile("mma.sync.aligned.m16n8k8.row.col.f32.tf32.tf32.f32 "
                 "{%0,%1,%2,%3}, {%4,%5,%6,%7}, {%8,%9}, {%0,%1,%2,%3};"
                 : "+f"(d0), "+f"(d1), "+f"(d2), "+f"(d3)
                 : "r"(a0), "r"(a1), "r"(a2), "r"(a3), "r"(b0), "r"(b1));
}
__device__ __forceinline__ void mma_bf16(float& d0, float& d1, float& d2, float& d3,
                                         unsigned a0, unsigned a1, unsigned a2, unsigned a3,
                                         unsigned b0, unsigned b1) {
    asm volatile("mma.sync.aligned.m16n8k16.row.col.f32.bf16.bf16.f32 "
                 "{%0,%1,%2,%3}, {%4,%5,%6,%7}, {%8,%9}, {%0,%1,%2,%3};"
                 : "+f"(d0), "+f"(d1), "+f"(d2), "+f"(d3)
                 : "r"(a0), "r"(a1), "r"(a2), "r"(a3), "r"(b0), "r"(b1));
}
struct __align__(16) BF8 { __nv_bfloat162 p[8]; };

// ---------------- CSR build ----------------
__global__ void init_small() {
    int i = blockIdx.x * blockDim.x + threadIdx.x;
    int st = gridDim.x * blockDim.x;
    for (int n = i; n < NN; n += st) { g_edeg[n] = 0; g_ddeg[n] = 0; }
    if (i == 0) { g_acc[0] = 0.0; g_acc[1] = 0.0; }
}
__global__ void build_deg(const int* __restrict__ dst, const int* __restrict__ pd) {
    int i = blockIdx.x * blockDim.x + threadIdx.x;
    int st = gridDim.x * blockDim.x;
    for (int e = i; e < E2; e += st) atomicAdd(&g_edeg[dst[e]], 1);
    for (int e = i; e < EP; e += st) atomicAdd(&g_ddeg[pd[e]], 1);
}
#define SCAN_CH 20
__global__ void scan2() {
    __shared__ int sp[1024];
    const int* deg = blockIdx.x ? g_ddeg : g_edeg;
    int* off = blockIdx.x ? g_doff : g_eoff;
    int* cur = blockIdx.x ? g_dcur : g_ecur;
    int t = threadIdx.x;
    int base = t * SCAN_CH;
    int loc[SCAN_CH];
    int s = 0;
#pragma unroll
    for (int i = 0; i < SCAN_CH; i++) {
        int n = base + i;
        loc[i] = (n < NN) ? deg[n] : 0;
        s += loc[i];
    }
    sp[t] = s;
    __syncthreads();
    for (int o = 1; o < 1024; o <<= 1) {
        int v = (t >= o) ? sp[t - o] : 0;
        __syncthreads();
        sp[t] += v;
        __syncthreads();
    }
    int excl = (t == 0) ? 0 : sp[t - 1];
#pragma unroll
    for (int i = 0; i < SCAN_CH; i++) {
        int n = base + i;
        if (n < NN) { off[n] = excl; cur[n] = excl; excl += loc[i]; }
    }
    if (t == 1023) off[NN] = sp[1023];
}
__global__ void build_fill(const int* __restrict__ src, const int* __restrict__ dst,
                           const int* __restrict__ ps, const int* __restrict__ pd) {
    int i = blockIdx.x * blockDim.x + threadIdx.x;
    int st = gridDim.x * blockDim.x;
    for (int e = i; e < E2; e += st) {
        int d = dst[e];
        int p = atomicAdd(&g_ecur[d], 1);
        g_esrc[p] = src[e];
    }
    for (int e = i; e < EP; e += st) {
        int d = pd[e];
        int p = atomicAdd(&g_dcur[d], 1);
        g_dsrc[p] = ps[e];
    }
    for (int n = i; n < NN; n += st) g_dis[n] = rsqrtf((float)g_ddeg[n] + 1.0f);
}

// ---------------- double-buffered tf32 GEMM ----------------
#define AS_S 36
#define WSG_S 72
__device__ __forceinline__ void gemm_db_body(
        const float* __restrict__ A, int lda,
        const float* __restrict__ W, int ldw,
        float* __restrict__ C, int ldc,
        __nv_bfloat16* __restrict__ Cb, int ldcb,
        int M, int Kin, int m0, int nb) {
    __shared__ float As[2][64 * AS_S];
    __shared__ float Ws[2][32 * WSG_S];
    int t = threadIdx.x;
    int w = t >> 5, lane = t & 31;
    int g = lane >> 2, t4 = lane & 3;
    int r0 = (w & 3) * 16, n0 = (w >> 2) * 32;
    int ar = t >> 2, ak = (t & 3) * 8;
    int wk = t >> 3, wn = (t & 7) * 8;
    int gm = m0 + ar;
    bool am = gm < M;
    float a_r[8], w_r[8];

#define LOAD_CHUNK(K0)                                                         \
    {                                                                          \
        if (am) {                                                              \
            const float* ap = &A[(size_t)gm * lda + (K0) + ak];                \
            float4 v0 = *(const float4*)ap;                                    \
            float4 v1 = *(const float4*)(ap + 4);                              \
            a_r[0] = v0.x; a_r[1] = v0.y; a_r[2] = v0.z; a_r[3] = v0.w;        \
            a_r[4] = v1.x; a_r[5] = v1.y; a_r[6] = v1.z; a_r[7] = v1.w;        \
        } else {                                                               \
            _Pragma("unroll") for (int i = 0; i < 8; i++) a_r[i] = 0.f;        \
        }                                                                      \
        const float* wp = &W[(size_t)((K0) + wk) * ldw + nb + wn];             \
        float4 u0 = *(const float4*)wp;                                        \
        float4 u1 = *(const float4*)(wp + 4);                                  \
        w_r[0] = u0.x; w_r[1] = u0.y; w_r[2] = u0.z; w_r[3] = u0.w;            \
        w_r[4] = u1.x; w_r[5] = u1.y; w_r[6] = u1.z; w_r[7] = u1.w;            \
    }
#define STORE_CHUNK(B)                                                         \
    {                                                                          \
        float* d = &As[B][ar * AS_S + ak];                                     \
        _Pragma("unroll") for (int i = 0; i < 8; i++)                          \
            d[i] = __uint_as_float(f2tf32(a_r[i]));                            \
        float* e = &Ws[B][wk * WSG_S + wn];                                    \
        _Pragma("unroll") for (int i = 0; i < 8; i++)                          \
            e[i] = __uint_as_float(f2tf32(w_r[i]));                            \
    }

    float acc[4][4];
#pragma unroll
    for (int s = 0; s < 4; s++)
#pragma unroll
        for (int j = 0; j < 4; j++) acc[s][j] = 0.f;

    LOAD_CHUNK(0)
    STORE_CHUNK(0)
    __syncthreads();

    int NC = Kin >> 5;
    for (int c = 0; c < NC; c++) {
        if (c + 1 < NC) LOAD_CHUNK((c + 1) * 32)
        int b = c & 1;
#pragma unroll
        for (int ks = 0; ks < 4; ks++) {
            int kk = ks * 8;
            unsigned a0 = __float_as_uint(As[b][(r0 + g) * AS_S + kk + t4]);
            unsigned a1 = __float_as_uint(As[b][(r0 + g + 8) * AS_S + kk + t4]);
            unsigned a2 = __float_as_uint(As[b][(r0 + g) * AS_S + kk + t4 + 4]);
            unsigned a3 = __float_as_uint(As[b][(r0 + g + 8) * AS_S + kk + t4 + 4]);
#pragma unroll
            for (int s = 0; s < 4; s++) {
                int n = n0 + s * 8 + g;
                unsigned b0 = __float_as_uint(Ws[b][(kk + t4) * WSG_S + n]);
                unsigned b1 = __float_as_uint(Ws[b][(kk + t4 + 4) * WSG_S + n]);
                mma_tf32(acc[s][0], acc[s][1], acc[s][2], acc[s][3],
                         a0, a1, a2, a3, b0, b1);
            }
        }
        if (c + 1 < NC) {
            __syncthreads();
            STORE_CHUNK((c + 1) & 1)
            __syncthreads();
        }
    }

    int gmA = m0 + r0 + g, gmB = gmA + 8;
#pragma unroll
    for (int s = 0; s < 4; s++) {
        int cn = n0 + s * 8 + t4 * 2;
        if (C) {
            if (gmA < M) *(float2*)&C[(size_t)gmA * ldc + cn] = make_float2(acc[s][0], acc[s][1]);
            if (gmB < M) *(float2*)&C[(size_t)gmB * ldc + cn] = make_float2(acc[s][2], acc[s][3]);
        }
        if (Cb) {
            if (gmA < M) *(__nv_bfloat162*)&Cb[(size_t)gmA * ldcb + cn] =
                __float22bfloat162_rn(make_float2(acc[s][0], acc[s][1]));
            if (gmB < M) *(__nv_bfloat162*)&Cb[(size_t)gmB * ldcb + cn] =
                __float22bfloat162_rn(make_float2(acc[s][2], acc[s][3]));
        }
    }
#undef LOAD_CHUNK
#undef STORE_CHUNK
}

__global__ void gemm_tf32(const float* __restrict__ A, int lda,
                          const float* __restrict__ W, int ldw,
                          float* __restrict__ C, int ldc,
                          int M, int Kin) {
    gemm_db_body(A, lda, W, ldw, C + blockIdx.y * 64, ldc, (__nv_bfloat16*)0, 0,
                 M, Kin, blockIdx.x * 64, blockIdx.y * 64);
}
__global__ void gemm_tf32_dual(const float* __restrict__ A, int lda,
                               const float* __restrict__ W0, const float* __restrict__ W1,
                               int ldw, float* __restrict__ C,
                               __nv_bfloat16* __restrict__ Cb, int ldc,
                               int M, int Kin) {
    const float* W = blockIdx.y ? W1 : W0;
    gemm_db_body(A, lda, W, ldw, C ? C + blockIdx.y * 64 : (float*)0, ldc,
                 Cb ? Cb + blockIdx.y * 64 : (__nv_bfloat16*)0, ldc,
                 M, Kin, blockIdx.x * 64, 0);
}

// ---------------- encoder layer-1 gather + bias + LN + relu ----------------
__global__ void gather_ln(const float* __restrict__ M1, const float* __restrict__ b1,
                          const float* __restrict__ g1, const float* __restrict__ bt1,
                          float* __restrict__ H1) {
    __shared__ float sred[256];
    int t = threadIdx.x;
    float bj = b1[t], gj = g1[t], btj = bt1[t];
    for (int d = blockIdx.x; d < NN; d += gridDim.x) {
        int beg = g_eoff[d], end = g_eoff[d + 1];
        float acc = bj;
        int i = beg;
        for (; i + 1 < end; i += 2) {
            int s0 = g_esrc[i], s1 = g_esrc[i + 1];
            acc += M1[(size_t)s0 * 256 + t] + M1[(size_t)s1 * 256 + t];
        }
        if (i < end) acc += M1[(size_t)g_esrc[i] * 256 + t];
        // LN over 256 cols
        sred[t] = acc;
        __syncthreads();
        for (int o = 128; o; o >>= 1) {
            if (t < o) sred[t] += sred[t + o];
            __syncthreads();
        }
        float mu = sred[0] * (1.f / 256.f);
        __syncthreads();
        float dv = acc - mu;
        sred[t] = dv * dv;
        __syncthreads();
        for (int o = 128; o; o >>= 1) {
            if (t < o) sred[t] += sred[t + o];
            __syncthreads();
        }
        float inv = rsqrtf(sred[0] * (1.f / 256.f) + LN_EPS);
        __syncthreads();
        H1[(size_t)d * 256 + t] = fmaxf(dv * inv * gj + btj, 0.f);
    }
}

// ---------------- encoder layer-2 gather + z + KL ----------------
__global__ void gather_zkl(const float* __restrict__ M2, const float* __restrict__ bmu,
                           const float* __restrict__ blv, const float* __restrict__ eps,
                           float* __restrict__ Z) {
    __shared__ float srow[128];
    int t = threadIdx.x;   // 128
    float bj = (t < 64) ? bmu[t] : blv[t - 64];
    float kl_loc = 0.f;
    for (int d = blockIdx.x; d < NN; d += gridDim.x) {
        int beg = g_eoff[d], end = g_eoff[d + 1];
        float acc = bj;
        int i = beg;
        for (; i + 1 < end; i += 2) {
            int s0 = g_esrc[i], s1 = g_esrc[i + 1];
            acc += M2[(size_t)s0 * 128 + t] + M2[(size_t)s1 * 128 + t];
        }
        if (i < end) acc += M2[(size_t)g_esrc[i] * 128 + t];
        srow[t] = acc;
        __syncthreads();
        if (t < 64) {
            float mu = srow[t], lv = srow[t + 64];
            Z[(size_t)d * 64 + t] = mu + eps[(size_t)d * 64 + t] * expf(0.5f * lv);
            kl_loc += 1.f + lv - mu * mu - expf(lv);
        }
        __syncthreads();
    }
    // reduce kl_loc over block
    srow[t] = kl_loc;
    __syncthreads();
    for (int o = 64; o; o >>= 1) {
        if (t < o) srow[t] += srow[t + o];
        __syncthreads();
    }
    if (t == 0) atomicAdd(&g_acc[0], (double)srow[0]);
}

// ---------------- decoder normalized gather + bias + relu ----------------
// block 256 = 4 nodes/iter (64 cols each)
__global__ void gather_dec(const float* __restrict__ M3, const float* __restrict__ bd,
                           float* __restrict__ Hf, __nv_bfloat16* __restrict__ Hb) {
    int t = threadIdx.x;
    int c = t & 63, sub = t >> 6;
    float bj = bd[c];
    for (int d0 = blockIdx.x * 4; d0 < NN; d0 += gridDim.x * 4) {
        int d = d0 + sub;
        if (d >= NN) continue;
        float dd = g_dis[d];
        float acc = dd * dd * M3[(size_t)d * 64 + c];
        int beg = g_doff[d], end = g_doff[d + 1];
        int i = beg;
        for (; i + 1 < end; i += 2) {
            int s0 = g_dsrc[i], s1 = g_dsrc[i + 1];
            acc += dd * g_dis[s0] * M3[(size_t)s0 * 64 + c]
                 + dd * g_dis[s1] * M3[(size_t)s1 * 64 + c];
        }
        if (i < end) {
            int s = g_dsrc[i];
            acc += dd * g_dis[s] * M3[(size_t)s * 64 + c];
        }
        float o = fmaxf(acc + bj, 0.f);
        Hf[(size_t)d * 64 + c] = o;
        if (Hb) Hb[(size_t)d * 64 + c] = __float2bfloat16(o);
    }
}

// ---------------- edge MLP + BCE (bf16 m16n8k16) ----------------
#define DS2_S 136
#define WS2_S 136
__global__ void edge_mlp_bf16(const __nv_bfloat16* __restrict__ h,
                              const __nv_bfloat16* __restrict__ P,
                              const int* __restrict__ pos, const int* __restrict__ neg,
                              const float* __restrict__ Wa, const float* __restrict__ ba,
                              const float* __restrict__ Wb, const float* __restrict__ bb,
                              const float* __restrict__ tau) {
    extern __shared__ char smraw[];
    float* red  = (float*)smraw;                 // 256
    float* sba  = red + 256;                     // 64
    float* sWb  = sba + 64;                      // 64
    float* slog = sWb + 64;                      // 64
    int*   su   = (int*)(slog + 64);             // 64
    int*   sv   = su + 64;                       // 64
    __nv_bfloat16* Ws2 = (__nv_bfloat16*)(sv + 64);
    __nv_bfloat16* Ds2 = Ws2 + 64 * WS2_S;

    int t = threadIdx.x;
    int w = t >> 5, lane = t & 31;
    int g = lane >> 2, t4 = lane & 3;
    int r0 = (w & 3) * 16;
    int n0 = (w >> 2) * 32;

    for (int i = t; i < 64 * 128; i += 256) {
        int n = i & 63, k = i >> 6;
        Ws2[n * WS2_S + k] = __float2bfloat16(Wa[(size_t)(128 + k) * 64 + n]);
    }
    if (t < 64) { sba[t] = ba[t]; sWb[t] = Wb[t]; }
    float tau_c = fmaxf(tau[0], 1e-4f);
    float bb0 = bb[0];
    float loc = 0.f;

    const int NTILES = ET / 64;
    for (int tb = blockIdx.x; tb < NTILES; tb += gridDim.x) {
        int e0 = tb * 64;
        __syncthreads();
        if (t < 64) {
            int e = e0 + t;
            if (e < EP) { su[t] = pos[e]; sv[t] = pos[EP + e]; }
            else        { su[t] = neg[e - EP]; sv[t] = neg[EN + (e - EP)]; }
            slog[t] = 0.f;
        }
        __syncthreads();

        {
            int ee = t >> 2, part = t & 3;
            int u = su[ee], v = sv[ee];
            BF8 hu8 = *(const BF8*)&h[(size_t)u * 64 + part * 16];
            BF8 hv8 = *(const BF8*)&h[(size_t)v * 64 + part * 16];
#pragma unroll
            for (int q = 0; q < 8; q++) {
                float2 a = __bfloat1622float2(hu8.p[q]);
                float2 b = __bfloat1622float2(hv8.p[q]);
                int kk = part * 16 + q * 2;
                *(__nv_bfloat162*)&Ds2[ee * DS2_S + kk] =
                    __float22bfloat162_rn(make_float2(fabsf(a.x - b.x), fabsf(a.y - b.y)));
                *(__nv_bfloat162*)&Ds2[ee * DS2_S + 64 + kk] =
                    __float22bfloat162_rn(make_float2(a.x * b.x, a.y * b.y));
            }
        }

        float acc[4][4];
        {
            int uA = su[r0 + g],     vA = sv[r0 + g];
            int uB = su[r0 + g + 8], vB = sv[r0 + g + 8];
#pragma unroll
            for (int s = 0; s < 4; s++) {
                int j0 = n0 + s * 8 + t4 * 2;
                float2 p1 = __bfloat1622float2(*(const __nv_bfloat162*)&P[(size_t)uA * 128 + j0]);
                float2 p2 = __bfloat1622float2(*(const __nv_bfloat162*)&P[(size_t)vA * 128 + 64 + j0]);
                acc[s][0] = p1.x + p2.x; acc[s][1] = p1.y + p2.y;
                float2 q1 = __bfloat1622float2(*(const __nv_bfloat162*)&P[(size_t)uB * 128 + j0]);
                float2 q2 = __bfloat1622float2(*(const __nv_bfloat162*)&P[(size_t)vB * 128 + 64 + j0]);
                acc[s][2] = q1.x + q2.x; acc[s][3] = q1.y + q2.y;
            }
        }
        __syncthreads();

#pragma unroll
        for (int ks = 0; ks < 8; ks++) {
            int k0 = ks * 16;
            unsigned a0 = *(const unsigned*)&Ds2[(r0 + g) * DS2_S + k0 + t4 * 2];
            unsigned a1 = *(const unsigned*)&Ds2[(r0 + g + 8) * DS2_S + k0 + t4 * 2];
            unsigned a2 = *(const unsigned*)&Ds2[(r0 + g) * DS2_S + k0 + t4 * 2 + 8];
            unsigned a3 = *(const unsigned*)&Ds2[(r0 + g + 8) * DS2_S + k0 + t4 * 2 + 8];
#pragma unroll
            for (int s = 0; s < 4; s++) {
                int n = n0 + s * 8 + g;
                unsigned b0 = *(const unsigned*)&Ws2[n * WS2_S + k0 + t4 * 2];
                unsigned b1 = *(const unsigned*)&Ws2[n * WS2_S + k0 + t4 * 2 + 8];
                mma_bf16(acc[s][0], acc[s][1], acc[s][2], acc[s][3],
                         a0, a1, a2, a3, b0, b1);
            }
        }

        {
            float p_lo = 0.f, p_hi = 0.f;
#pragma unroll
            for (int s = 0; s < 4; s++) {
                int j0 = n0 + s * 8 + t4 * 2;
                p_lo += fmaxf(acc[s][0] + sba[j0], 0.f) * sWb[j0]
                      + fmaxf(acc[s][1] + sba[j0 + 1], 0.f) * sWb[j0 + 1];
                p_hi += fmaxf(acc[s][2] + sba[j0], 0.f) * sWb[j0]
                      + fmaxf(acc[s][3] + sba[j0 + 1], 0.f) * sWb[j0 + 1];
            }
            p_lo += __shfl_down_sync(0xffffffffu, p_lo, 2, 4);
            p_lo += __shfl_down_sync(0xffffffffu, p_lo, 1, 4);
            p_hi += __shfl_down_sync(0xffffffffu, p_hi, 2, 4);
            p_hi += __shfl_down_sync(0xffffffffu, p_hi, 1, 4);
            if (t4 == 0) {
                atomicAdd(&slog[r0 + g], p_lo);
                atomicAdd(&slog[r0 + g + 8], p_hi);
            }
        }
        __syncthreads();

        if (t < 64) {
            float l = (slog[t] + bb0) / tau_c;
            int ge = e0 + t;
            loc += (ge < EP) ? (-5.0f * logsig(l)) : (-logsig(-l));
        }
    }
    __syncthreads();
    red[t] = loc;
    __syncthreads();
    for (int o = 128; o; o >>= 1) {
        if (t < o) red[t] += red[t + o];
        __syncthreads();
    }
    if (t == 0) atomicAdd(&g_acc[1], (double)red[0]);
}

// ---------------- finalize ----------------
__global__ void finalize_k(float* out, int out_size) {
    double kl = -0.5 * g_acc[0] / (double)(NN * 64);
    double recon = g_acc[1] / (double)ET;
    if (out_size >= 3) {
        out[0] = (float)(recon + kl);
        out[1] = (float)recon;
        out[2] = (float)kl;
    } else {
        out[0] = (float)(recon + kl);
    }
}

// ---------------- launch ----------------
extern "C" void kernel_launch(void* const* d_in, const int* in_sizes, int n_in,
                              void* d_out, int out_size) {
    const float* x    = (const float*)d_in[0];
    const float* eps  = (const float*)d_in[1];
    const int* ei     = (const int*)d_in[2];
    const int* pos    = (const int*)d_in[3];
    const int* neg    = (const int*)d_in[4];
    const float* W1   = (const float*)d_in[5];
    const float* b1   = (const float*)d_in[6];
    const float* g1   = (const float*)d_in[7];
    const float* bt1  = (const float*)d_in[8];
    const float* Wmu  = (const float*)d_in[9];
    const float* bmu  = (const float*)d_in[10];
    const float* Wlv  = (const float*)d_in[11];
    const float* blv  = (const float*)d_in[12];
    const float* Wd1  = (const float*)d_in[13];
    const float* bd1  = (const float*)d_in[14];
    const float* Wd2  = (const float*)d_in[15];
    const float* bd2  = (const float*)d_in[16];
    const float* Wa   = (const float*)d_in[17];
    const float* ba   = (const float*)d_in[18];
    const float* Wb   = (const float*)d_in[19];
    const float* bb   = (const float*)d_in[20];
    const float* tau  = (const float*)d_in[21];
    float* out = (float*)d_out;

    const int* src = ei;
    const int* dst = ei + E2;
    const int* ps  = pos;
    const int* pd  = pos + EP;

    float *M1, *H1, *M2, *Z, *M3, *HD1, *HF;
    __nv_bfloat16 *Hbf, *Pbf;
    cudaGetSymbolAddress((void**)&M1, g_M1);
    cudaGetSymbolAddress((void**)&H1, g_H1);
    cudaGetSymbolAddress((void**)&M2, g_M2);
    cudaGetSymbolAddress((void**)&Z,  g_Z);
    cudaGetSymbolAddress((void**)&M3, g_M3);
    cudaGetSymbolAddress((void**)&HD1, g_HD1);
    cudaGetSymbolAddress((void**)&HF, g_HF);
    cudaGetSymbolAddress((void**)&Hbf, g_Hbf);
    cudaGetSymbolAddress((void**)&Pbf, g_Pbf);

    const int EDGE_SMEM = (256 + 64 * 3) * 4 + 128 * 4 + (64 * WS2_S + 64 * DS2_S) * 2;
    cudaFuncSetAttribute(edge_mlp_bf16, cudaFuncAttributeMaxDynamicSharedMemorySize, EDGE_SMEM);

    const int GM = (NN + 63) / 64;   // 313

    // CSR build
    init_small<<<40, 512>>>();
    build_deg<<<256, 256>>>(dst, pd);
    scan2<<<2, 1024>>>();
    // big GEMM first (independent of CSR fill)
    gemm_tf32<<<dim3(GM, 4), 256>>>(x, 256, W1, 256, M1, 256, NN, 256);
    build_fill<<<256, 256>>>(src, dst, ps, pd);

    // encoder layer 1: gather + bias + LN + relu
    gather_ln<<<2960, 256>>>(M1, b1, g1, bt1, H1);

    // encoder layer 2
    gemm_tf32_dual<<<dim3(GM, 2), 256>>>(H1, 256, Wmu, Wlv, 64, M2, nullptr, 128, NN, 256);
    gather_zkl<<<2960, 128>>>(M2, bmu, blv, eps, Z);

    // decoder pass 1
    gemm_tf32<<<dim3(GM, 1), 256>>>(Z, 64, Wd1, 64, M3, 64, NN, 64);
    gather_dec<<<1480, 256>>>(M3, bd1, HD1, nullptr);

    // decoder pass 2
    gemm_tf32<<<dim3(GM, 1), 256>>>(HD1, 64, Wd2, 64, M3, 64, NN, 64);
    gather_dec<<<1480, 256>>>(M3, bd2, HF, Hbf);

    // P = [h@Wa1 | h@Wa2] (bf16)
    gemm_tf32_dual<<<dim3(GM, 2), 256>>>(HF, 64, Wa, Wa + 64 * 64, 64,
                                         nullptr, Pbf, 128, NN, 64);

    edge_mlp_bf16<<<592, 256, EDGE_SMEM>>>(Hbf, Pbf, pos, neg, Wa, ba, Wb, bb, tau);

    finalize_k<<<1, 1>>>(out, out_size);
}

// round 10
// speedup vs baseline: 1.0483x; 1.0483x over previous
#include <cuda_runtime.h>
#include <cuda_bf16.h>
#include <math.h>

// ---------------- problem constants ----------------
#define NN      20000
#define EP      120000
#define EN      600000
#define ET      720000
#define E2      240000
#define LN_EPS  1e-5f

// ---------------- scratch ----------------
__device__ float  g_M1[NN * 256];
__device__ float  g_A1[NN * 256];
__device__ float  g_H1[NN * 256];
__device__ float  g_M2[NN * 128];
__device__ float  g_A2[NN * 128];
__device__ float  g_Z [NN * 64];
__device__ float  g_M3[NN * 64];
__device__ float  g_A3a[NN * 64];
__device__ float  g_A3b[NN * 64];
__device__ __nv_bfloat16 g_Hbf[NN * 64];
__device__ __nv_bfloat16 g_Pbf[NN * 128];
__device__ int    g_deg[NN];
__device__ float  g_dis[NN];
__device__ double g_acc[2];

// ---------------- helpers ----------------
__device__ __forceinline__ void red4(float* p, float x, float y, float z, float w) {
    asm volatile("red.global.add.v4.f32 [%0], {%1,%2,%3,%4};"
                 :: "l"(p), "f"(x), "f"(y), "f"(z), "f"(w) : "memory");
}
__device__ __forceinline__ float logsig(float x) {
    return fminf(x, 0.0f) - log1pf(expf(-fabsf(x)));
}
__device__ __forceinline__ unsigned f2tf32(float x) {
    unsigned r;
    asm("cvt.rna.tf32.f32 %0, %1;" : "=r"(r) : "f"(x));
    return r;
}
__device__ __forceinline__ void mma_tf32(float& d0, float& d1, float& d2, float& d3,
                                         unsigned a0, unsigned a1, unsigned a2, unsigned a3,
                                         unsigned b0, unsigned b1) {
    asm volatile("mma.sync.aligned.m16n8k8.row.col.f32.tf32.tf32.f32 "
                 "{%0,%1,%2,%3}, {%4,%5,%6,%7}, {%8,%9}, {%0,%1,%2,%3};"
                 : "+f"(d0), "+f"(d1), "+f"(d2), "+f"(d3)
                 : "r"(a0), "r"(a1), "r"(a2), "r"(a3), "r"(b0), "r"(b1));
}
__device__ __forceinline__ void mma_bf16(float& d0, float& d1, float& d2, float& d3,
                                         unsigned a0, unsigned a1, unsigned a2, unsigned a3,
                                         unsigned b0, unsigned b1) {
    asm volatile("mma.sync.aligned.m16n8k16.row.col.f32.bf16.bf16.f32 "
                 "{%0,%1,%2,%3}, {%4,%5,%6,%7}, {%8,%9}, {%0,%1,%2,%3};"
                 : "+f"(d0), "+f"(d1), "+f"(d2), "+f"(d3)
                 : "r"(a0), "r"(a1), "r"(a2), "r"(a3), "r"(b0), "r"(b1));
}
struct __align__(16) BF8 { __nv_bfloat162 p[8]; };

// ---------------- zero scratch ----------------
__global__ void zero_all() {
    size_t i = (size_t)blockIdx.x * blockDim.x + threadIdx.x;
    size_t st = (size_t)gridDim.x * blockDim.x;
    for (size_t k = i; k < (size_t)NN * 256; k += st) g_A1[k] = 0.f;
    for (size_t k = i; k < (size_t)NN * 128; k += st) g_A2[k] = 0.f;
    for (size_t k = i; k < NN; k += st) g_deg[k] = 0;
    if (i == 0) { g_acc[0] = 0.0; g_acc[1] = 0.0; }
}

// ---------------- tf32 GEMM, paired-k fragment layout, 1 sync/chunk ----------
// Tile 64x64, 8 warps (warp w: rows (w&3)*16, cols (w>>2)*32), K chunks of 32.
// Layouts (stride 40 floats): As2[r][k0 + 2*(j&3) + (j>>2)] for k=k0+j;
//                             Ws2[n][same k mapping].
// All fragment reads are LDS.64, bank-conflict-free (20g + t4 distinct mod 16).
#define GS 40
__device__ __forceinline__ void gemm_db_body(
        const float* __restrict__ A, int lda,
        const float* __restrict__ W, int ldw,
        float* __restrict__ C, int ldc,
        __nv_bfloat16* __restrict__ Cb, int ldcb,
        int M, int Kin, int m0, int nb,
        const float* __restrict__ abias) {
    __shared__ float As2[2][64 * GS];
    __shared__ float Ws2[2][64 * GS];
    int t = threadIdx.x;
    int w = t >> 5, lane = t & 31;
    int g = lane >> 2, t4 = lane & 3;
    int r0 = (w & 3) * 16, n0 = (w >> 2) * 32;
    // A staging: row ar, k-chunk ak
    int ar = t >> 2, ak = (t & 3) * 8;
    // W staging: k-row wk (0..31), n = wn + 8i
    int wk = t >> 3, wn = t & 7;
    int wpos = (wk & 24) + 2 * (wk & 3) + ((wk >> 2) & 1);
    int gm = m0 + ar;
    bool am = gm < M;
    float a_r[8], w_r[8];

#define LOAD_CHUNK(K0)                                                         \
    {                                                                          \
        if (am) {                                                              \
            const float* ap = &A[(size_t)gm * lda + (K0) + ak];                \
            float4 v0 = *(const float4*)ap;                                    \
            float4 v1 = *(const float4*)(ap + 4);                              \
            a_r[0] = v0.x; a_r[1] = v0.y; a_r[2] = v0.z; a_r[3] = v0.w;        \
            a_r[4] = v1.x; a_r[5] = v1.y; a_r[6] = v1.z; a_r[7] = v1.w;        \
        } else {                                                               \
            _Pragma("unroll") for (int i = 0; i < 8; i++) a_r[i] = 0.f;        \
        }                                                                      \
        if (abias) {                                                           \
            _Pragma("unroll") for (int i = 0; i < 8; i++)                      \
                a_r[i] = fmaxf(a_r[i] + abias[(K0) + ak + i], 0.f);            \
        }                                                                      \
        const float* wp = &W[(size_t)((K0) + wk) * ldw + nb + wn];             \
        _Pragma("unroll") for (int i = 0; i < 8; i++) w_r[i] = wp[8 * i];      \
    }
#define STORE_CHUNK(B)                                                         \
    {                                                                          \
        float* d = &As2[B][ar * GS + ak];                                      \
        _Pragma("unroll") for (int j = 0; j < 4; j++) {                        \
            float2 pr;                                                         \
            pr.x = __uint_as_float(f2tf32(a_r[j]));                            \
            pr.y = __uint_as_float(f2tf32(a_r[j + 4]));                        \
            *(float2*)&d[2 * j] = pr;                                          \
        }                                                                      \
        _Pragma("unroll") for (int i = 0; i < 8; i++)                          \
            Ws2[B][(wn + 8 * i) * GS + wpos] = __uint_as_float(f2tf32(w_r[i]));\
    }

    float acc[4][4];
#pragma unroll
    for (int s = 0; s < 4; s++)
#pragma unroll
        for (int j = 0; j < 4; j++) acc[s][j] = 0.f;

    LOAD_CHUNK(0)
    STORE_CHUNK(0)
    __syncthreads();

    int NC = Kin >> 5;
    for (int c = 0; c < NC; c++) {
        if (c + 1 < NC) LOAD_CHUNK((c + 1) * 32)
        int b = c & 1;
#pragma unroll
        for (int ks = 0; ks < 4; ks++) {
            int kk = ks * 8;
            float2 aA = *(const float2*)&As2[b][(r0 + g) * GS + kk + 2 * t4];
            float2 aB = *(const float2*)&As2[b][(r0 + g + 8) * GS + kk + 2 * t4];
            unsigned a0 = __float_as_uint(aA.x), a1 = __float_as_uint(aB.x);
            unsigned a2 = __float_as_uint(aA.y), a3 = __float_as_uint(aB.y);
#pragma unroll
            for (int s = 0; s < 4; s++) {
                int n = n0 + s * 8 + g;
                float2 bv = *(const float2*)&Ws2[b][n * GS + kk + 2 * t4];
                mma_tf32(acc[s][0], acc[s][1], acc[s][2], acc[s][3],
                         a0, a1, a2, a3,
                         __float_as_uint(bv.x), __float_as_uint(bv.y));
            }
        }
        if (c + 1 < NC) {
            STORE_CHUNK((c + 1) & 1)
            __syncthreads();
        }
    }

    int gmA = m0 + r0 + g, gmB = gmA + 8;
#pragma unroll
    for (int s = 0; s < 4; s++) {
        int cn = n0 + s * 8 + t4 * 2;
        if (C) {
            if (gmA < M) *(float2*)&C[(size_t)gmA * ldc + cn] = make_float2(acc[s][0], acc[s][1]);
            if (gmB < M) *(float2*)&C[(size_t)gmB * ldc + cn] = make_float2(acc[s][2], acc[s][3]);
        }
        if (Cb) {
            if (gmA < M) *(__nv_bfloat162*)&Cb[(size_t)gmA * ldcb + cn] =
                __float22bfloat162_rn(make_float2(acc[s][0], acc[s][1]));
            if (gmB < M) *(__nv_bfloat162*)&Cb[(size_t)gmB * ldcb + cn] =
                __float22bfloat162_rn(make_float2(acc[s][2], acc[s][3]));
        }
    }
#undef LOAD_CHUNK
#undef STORE_CHUNK
}

__global__ void gemm_tf32(const float* __restrict__ A, int lda,
                          const float* __restrict__ W, int ldw,
                          float* __restrict__ C, int ldc,
                          int M, int Kin, const float* __restrict__ abias) {
    gemm_db_body(A, lda, W, ldw, C + blockIdx.y * 64, ldc, (__nv_bfloat16*)0, 0,
                 M, Kin, blockIdx.x * 64, blockIdx.y * 64, abias);
}
__global__ void gemm_tf32_dual(const float* __restrict__ A, int lda,
                               const float* __restrict__ W0, const float* __restrict__ W1,
                               int ldw, float* __restrict__ C,
                               __nv_bfloat16* __restrict__ Cb, int ldc,
                               int M, int Kin, const float* __restrict__ abias) {
    const float* W = blockIdx.y ? W1 : W0;
    gemm_db_body(A, lda, W, ldw, C ? C + blockIdx.y * 64 : (float*)0, ldc,
                 Cb ? Cb + blockIdx.y * 64 : (__nv_bfloat16*)0, ldc,
                 M, Kin, blockIdx.x * 64, 0, abias);
}

// ---------------- scatter-add ----------------
__global__ void scatter_add(const float* __restrict__ M, const int* __restrict__ src,
                            const int* __restrict__ dst, float* __restrict__ A,
                            int nE, int F4) {
    int gt = blockIdx.x * blockDim.x + threadIdx.x;
    int e = gt >> 5, lane = gt & 31;
    if (e >= nE) return;
    int s = src[e], d = dst[e];
    const float4* Mr = (const float4*)&M[(size_t)s * (F4 * 4)];
    float* Ar = &A[(size_t)d * (F4 * 4)];
    for (int c = lane; c < F4; c += 32) {
        float4 v = Mr[c];
        red4(Ar + c * 4, v.x, v.y, v.z, v.w);
    }
}

// ---------------- LayerNorm + ReLU ----------------
__global__ void ln_relu(const float* __restrict__ A, const float* __restrict__ b,
                        const float* __restrict__ g, const float* __restrict__ bt,
                        float* __restrict__ H) {
    int w = (blockIdx.x * blockDim.x + threadIdx.x) >> 5;
    int lane = threadIdx.x & 31;
    if (w >= NN) return;
    float v[8];
    float s = 0.f;
#pragma unroll
    for (int i = 0; i < 8; i++) {
        int j = i * 32 + lane;
        v[i] = A[(size_t)w * 256 + j] + b[j];
        s += v[i];
    }
#pragma unroll
    for (int o = 16; o; o >>= 1) s += __shfl_xor_sync(0xffffffffu, s, o);
    float mu = s * (1.f / 256.f);
    float s2 = 0.f;
#pragma unroll
    for (int i = 0; i < 8; i++) { float d = v[i] - mu; s2 += d * d; }
#pragma unroll
    for (int o = 16; o; o >>= 1) s2 += __shfl_xor_sync(0xffffffffu, s2, o);
    float inv = rsqrtf(s2 * (1.f / 256.f) + LN_EPS);
#pragma unroll
    for (int i = 0; i < 8; i++) {
        int j = i * 32 + lane;
        H[(size_t)w * 256 + j] = fmaxf((v[i] - mu) * inv * g[j] + bt[j], 0.f);
    }
}

// ---------------- z = mu + eps*exp(0.5 lv); KL ----------------
__global__ void z_kl(const float* __restrict__ A2, const float* __restrict__ bmu,
                     const float* __restrict__ blv, const float* __restrict__ eps,
                     float* __restrict__ Z) {
    __shared__ float red[256];
    int idx = blockIdx.x * blockDim.x + threadIdx.x;
    float t = 0.f;
    if (idx < NN * 64) {
        int n = idx >> 6, j = idx & 63;
        float mu = A2[(size_t)n * 128 + j] + bmu[j];
        float lv = A2[(size_t)n * 128 + 64 + j] + blv[j];
        Z[idx] = mu + eps[idx] * expf(0.5f * lv);
        t = 1.f + lv - mu * mu - expf(lv);
    }
    red[threadIdx.x] = t;
    __syncthreads();
    for (int o = 128; o; o >>= 1) {
        if (threadIdx.x < o) red[threadIdx.x] += red[threadIdx.x + o];
        __syncthreads();
    }
    if (threadIdx.x == 0) atomicAdd(&g_acc[0], (double)red[0]);
}

// ---------------- decoder degree / dis ----------------
__global__ void deg_count(const int* __restrict__ pd) {
    int e = blockIdx.x * blockDim.x + threadIdx.x;
    if (e < EP) atomicAdd(&g_deg[pd[e]], 1);
}
__global__ void dis_kernel() {
    int n = blockIdx.x * blockDim.x + threadIdx.x;
    if (n < NN) g_dis[n] = rsqrtf((float)g_deg[n] + 1.0f);
}

// ---------------- normalized scatter ----------------
__global__ void scatter_norm(const float* __restrict__ M, const int* __restrict__ ps,
                             const int* __restrict__ pd, float* __restrict__ A) {
    int idx = blockIdx.x * blockDim.x + threadIdx.x;
    int e = idx >> 4, c = idx & 15;
    if (e >= EP + NN) return;
    int s, d; float coef;
    if (e < EP) { s = ps[e]; d = pd[e]; coef = g_dis[s] * g_dis[d]; }
    else        { s = d = e - EP; float x = g_dis[s]; coef = x * x; }
    float4 v = *(const float4*)&M[(size_t)s * 64 + c * 4];
    red4(&A[(size_t)d * 64 + c * 4], v.x * coef, v.y * coef, v.z * coef, v.w * coef);
}

// ---------------- zero decoder accums ----------------
__global__ void zero_dec() {
    size_t i = (size_t)blockIdx.x * blockDim.x + threadIdx.x;
    size_t st = (size_t)gridDim.x * blockDim.x;
    for (size_t k = i; k < (size_t)NN * 64; k += st) { g_A3a[k] = 0.f; g_A3b[k] = 0.f; }
}

// ---------------- bias+relu -> bf16 ----------------
__global__ void bias_relu_bf16(const float* __restrict__ A, const float* __restrict__ b,
                               __nv_bfloat16* __restrict__ H) {
    int idx = blockIdx.x * blockDim.x + threadIdx.x;
    if (idx < NN * 32) {
        int base = idx * 2;
        float2 v;
        v.x = fmaxf(A[base] + b[base & 63], 0.f);
        v.y = fmaxf(A[base + 1] + b[(base + 1) & 63], 0.f);
        *(__nv_bfloat162*)&H[base] = __float22bfloat162_rn(v);
    }
}

// ---------------- edge MLP + BCE (bf16 m16n8k16) ----------------
#define DS2_S 136
#define WS2_S 136
__global__ void edge_mlp_bf16(const __nv_bfloat16* __restrict__ h,
                              const __nv_bfloat16* __restrict__ P,
                              const int* __restrict__ pos, const int* __restrict__ neg,
                              const float* __restrict__ Wa, const float* __restrict__ ba,
                              const float* __restrict__ Wb, const float* __restrict__ bb,
                              const float* __restrict__ tau) {
    extern __shared__ char smraw[];
    float* red  = (float*)smraw;
    float* sba  = red + 256;
    float* sWb  = sba + 64;
    float* slog = sWb + 64;
    int*   su   = (int*)(slog + 64);
    int*   sv   = su + 64;
    __nv_bfloat16* Ws2 = (__nv_bfloat16*)(sv + 64);
    __nv_bfloat16* Ds2 = Ws2 + 64 * WS2_S;

    int t = threadIdx.x;
    int w = t >> 5, lane = t & 31;
    int g = lane >> 2, t4 = lane & 3;
    int r0 = (w & 3) * 16;
    int n0 = (w >> 2) * 32;

    for (int i = t; i < 64 * 128; i += 256) {
        int n = i & 63, k = i >> 6;
        Ws2[n * WS2_S + k] = __float2bfloat16(Wa[(size_t)(128 + k) * 64 + n]);
    }
    if (t < 64) { sba[t] = ba[t]; sWb[t] = Wb[t]; }
    float tau_c = fmaxf(tau[0], 1e-4f);
    float bb0 = bb[0];
    float loc = 0.f;

    const int NTILES = ET / 64;
    for (int tb = blockIdx.x; tb < NTILES; tb += gridDim.x) {
        int e0 = tb * 64;
        __syncthreads();
        if (t < 64) {
            int e = e0 + t;
            if (e < EP) { su[t] = pos[e]; sv[t] = pos[EP + e]; }
            else        { su[t] = neg[e - EP]; sv[t] = neg[EN + (e - EP)]; }
            slog[t] = 0.f;
        }
        __syncthreads();

        {
            int ee = t >> 2, part = t & 3;
            int u = su[ee], v = sv[ee];
            BF8 hu8 = *(const BF8*)&h[(size_t)u * 64 + part * 16];
            BF8 hv8 = *(const BF8*)&h[(size_t)v * 64 + part * 16];
#pragma unroll
            for (int q = 0; q < 8; q++) {
                float2 a = __bfloat1622float2(hu8.p[q]);
                float2 b = __bfloat1622float2(hv8.p[q]);
                int kk = part * 16 + q * 2;
                *(__nv_bfloat162*)&Ds2[ee * DS2_S + kk] =
                    __float22bfloat162_rn(make_float2(fabsf(a.x - b.x), fabsf(a.y - b.y)));
                *(__nv_bfloat162*)&Ds2[ee * DS2_S + 64 + kk] =
                    __float22bfloat162_rn(make_float2(a.x * b.x, a.y * b.y));
            }
        }

        float acc[4][4];
        {
            int uA = su[r0 + g],     vA = sv[r0 + g];
            int uB = su[r0 + g + 8], vB = sv[r0 + g + 8];
#pragma unroll
            for (int s = 0; s < 4; s++) {
                int j0 = n0 + s * 8 + t4 * 2;
                float2 p1 = __bfloat1622float2(*(const __nv_bfloat162*)&P[(size_t)uA * 128 + j0]);
                float2 p2 = __bfloat1622float2(*(const __nv_bfloat162*)&P[(size_t)vA * 128 + 64 + j0]);
                acc[s][0] = p1.x + p2.x; acc[s][1] = p1.y + p2.y;
                float2 q1 = __bfloat1622float2(*(const __nv_bfloat162*)&P[(size_t)uB * 128 + j0]);
                float2 q2 = __bfloat1622float2(*(const __nv_bfloat162*)&P[(size_t)vB * 128 + 64 + j0]);
                acc[s][2] = q1.x + q2.x; acc[s][3] = q1.y + q2.y;
            }
        }
        __syncthreads();

#pragma unroll
        for (int ks = 0; ks < 8; ks++) {
            int k0 = ks * 16;
            unsigned a0 = *(const unsigned*)&Ds2[(r0 + g) * DS2_S + k0 + t4 * 2];
            unsigned a1 = *(const unsigned*)&Ds2[(r0 + g + 8) * DS2_S + k0 + t4 * 2];
            unsigned a2 = *(const unsigned*)&Ds2[(r0 + g) * DS2_S + k0 + t4 * 2 + 8];
            unsigned a3 = *(const unsigned*)&Ds2[(r0 + g + 8) * DS2_S + k0 + t4 * 2 + 8];
#pragma unroll
            for (int s = 0; s < 4; s++) {
                int n = n0 + s * 8 + g;
                unsigned b0 = *(const unsigned*)&Ws2[n * WS2_S + k0 + t4 * 2];
                unsigned b1 = *(const unsigned*)&Ws2[n * WS2_S + k0 + t4 * 2 + 8];
                mma_bf16(acc[s][0], acc[s][1], acc[s][2], acc[s][3],
                         a0, a1, a2, a3, b0, b1);
            }
        }

        {
            float p_lo = 0.f, p_hi = 0.f;
#pragma unroll
            for (int s = 0; s < 4; s++) {
                int j0 = n0 + s * 8 + t4 * 2;
                p_lo += fmaxf(acc[s][0] + sba[j0], 0.f) * sWb[j0]
                      + fmaxf(acc[s][1] + sba[j0 + 1], 0.f) * sWb[j0 + 1];
                p_hi += fmaxf(acc[s][2] + sba[j0], 0.f) * sWb[j0]
                      + fmaxf(acc[s][3] + sba[j0 + 1], 0.f) * sWb[j0 + 1];
            }
            p_lo += __shfl_down_sync(0xffffffffu, p_lo, 2, 4);
            p_lo += __shfl_down_sync(0xffffffffu, p_lo, 1, 4);
            p_hi += __shfl_down_sync(0xffffffffu, p_hi, 2, 4);
            p_hi += __shfl_down_sync(0xffffffffu, p_hi, 1, 4);
            if (t4 == 0) {
                atomicAdd(&slog[r0 + g], p_lo);
                atomicAdd(&slog[r0 + g + 8], p_hi);
            }
        }
        __syncthreads();

        if (t < 64) {
            float l = (slog[t] + bb0) / tau_c;
            int ge = e0 + t;
            loc += (ge < EP) ? (-5.0f * logsig(l)) : (-logsig(-l));
        }
    }
    __syncthreads();
    red[t] = loc;
    __syncthreads();
    for (int o = 128; o; o >>= 1) {
        if (t < o) red[t] += red[t + o];
        __syncthreads();
    }
    if (t == 0) atomicAdd(&g_acc[1], (double)red[0]);
}

// ---------------- finalize ----------------
__global__ void finalize_k(float* out, int out_size) {
    double kl = -0.5 * g_acc[0] / (double)(NN * 64);
    double recon = g_acc[1] / (double)ET;
    if (out_size >= 3) {
        out[0] = (float)(recon + kl);
        out[1] = (float)recon;
        out[2] = (float)kl;
    } else {
        out[0] = (float)(recon + kl);
    }
}

// ---------------- launch ----------------
extern "C" void kernel_launch(void* const* d_in, const int* in_sizes, int n_in,
                              void* d_out, int out_size) {
    const float* x    = (const float*)d_in[0];
    const float* eps  = (const float*)d_in[1];
    const int* ei     = (const int*)d_in[2];
    const int* pos    = (const int*)d_in[3];
    const int* neg    = (const int*)d_in[4];
    const float* W1   = (const float*)d_in[5];
    const float* b1   = (const float*)d_in[6];
    const float* g1   = (const float*)d_in[7];
    const float* bt1  = (const float*)d_in[8];
    const float* Wmu  = (const float*)d_in[9];
    const float* bmu  = (const float*)d_in[10];
    const float* Wlv  = (const float*)d_in[11];
    const float* blv  = (const float*)d_in[12];
    const float* Wd1  = (const float*)d_in[13];
    const float* bd1  = (const float*)d_in[14];
    const float* Wd2  = (const float*)d_in[15];
    const float* bd2  = (const float*)d_in[16];
    const float* Wa   = (const float*)d_in[17];
    const float* ba   = (const float*)d_in[18];
    const float* Wb   = (const float*)d_in[19];
    const float* bb   = (const float*)d_in[20];
    const float* tau  = (const float*)d_in[21];
    float* out = (float*)d_out;

    const int* src = ei;
    const int* dst = ei + E2;
    const int* ps  = pos;
    const int* pd  = pos + EP;

    float *M1, *A1, *H1, *M2, *A2, *Z, *M3, *A3a, *A3b;
    __nv_bfloat16 *Hbf, *Pbf;
    cudaGetSymbolAddress((void**)&M1, g_M1);
    cudaGetSymbolAddress((void**)&A1, g_A1);
    cudaGetSymbolAddress((void**)&H1, g_H1);
    cudaGetSymbolAddress((void**)&M2, g_M2);
    cudaGetSymbolAddress((void**)&A2, g_A2);
    cudaGetSymbolAddress((void**)&Z,  g_Z);
    cudaGetSymbolAddress((void**)&M3, g_M3);
    cudaGetSymbolAddress((void**)&A3a, g_A3a);
    cudaGetSymbolAddress((void**)&A3b, g_A3b);
    cudaGetSymbolAddress((void**)&Hbf, g_Hbf);
    cudaGetSymbolAddress((void**)&Pbf, g_Pbf);

    const int EDGE_SMEM = (256 + 64 * 3) * 4 + 128 * 4 + (64 * WS2_S + 64 * DS2_S) * 2;
    cudaFuncSetAttribute(edge_mlp_bf16, cudaFuncAttributeMaxDynamicSharedMemorySize, EDGE_SMEM);

    zero_all<<<2048, 256>>>();
    zero_dec<<<1024, 256>>>();

    const int GM = (NN + 63) / 64;   // 313
    gemm_tf32<<<dim3(GM, 4), 256>>>(x, 256, W1, 256, M1, 256, NN, 256, nullptr);

    scatter_add<<<(E2 * 32 + 255) / 256, 256>>>(M1, src, dst, A1, E2, 64);
    ln_relu<<<(NN * 32 + 255) / 256, 256>>>(A1, b1, g1, bt1, H1);

    gemm_tf32_dual<<<dim3(GM, 2), 256>>>(H1, 256, Wmu, Wlv, 64, M2, nullptr, 128, NN, 256, nullptr);
    scatter_add<<<(E2 * 32 + 255) / 256, 256>>>(M2, src, dst, A2, E2, 32);
    z_kl<<<(NN * 64 + 255) / 256, 256>>>(A2, bmu, blv, eps, Z);

    deg_count<<<(EP + 255) / 256, 256>>>(pd);
    dis_kernel<<<(NN + 255) / 256, 256>>>();

    gemm_tf32<<<dim3(GM, 1), 256>>>(Z, 64, Wd1, 64, M3, 64, NN, 64, nullptr);
    scatter_norm<<<((EP + NN) * 16 + 255) / 256, 256>>>(M3, ps, pd, A3a);

    gemm_tf32<<<dim3(GM, 1), 256>>>(A3a, 64, Wd2, 64, M3, 64, NN, 64, bd1);
    scatter_norm<<<((EP + NN) * 16 + 255) / 256, 256>>>(M3, ps, pd, A3b);

    bias_relu_bf16<<<(NN * 32 + 255) / 256, 256>>>(A3b, bd2, Hbf);
    gemm_tf32_dual<<<dim3(GM, 2), 256>>>(A3b, 64, Wa, Wa + 64 * 64, 64,
                                         nullptr, Pbf, 128, NN, 64, bd2);

    edge_mlp_bf16<<<592, 256, EDGE_SMEM>>>(Hbf, Pbf, pos, neg, Wa, ba, Wb, bb, tau);

    finalize_k<<<1, 1>>>(out, out_size);
}